// round 7
// baseline (speedup 1.0000x reference)
#include <cuda_runtime.h>

// WaveletSparsityLoss: 3-level Haar DWT sparsity loss on [32,1,1024,1024] fp32.
// Streaming config identical to R1 (fastest measured: 2048 blocks, 1 tile per
// thread, fully unrolled loads). Fused last-block reduction handled by warp 0
// ONLY after the single block barrier -> warps 1..7 retire immediately, so the
// fusion adds ~0 cost to block turnover (R2/R4/R6 regressions came from all
// warps waiting on thread 0's ATOMG at a second barrier).

#define IMG          1024
#define TILES_X      128                    // 1024/8
#define TILES_PER_IMG (TILES_X * TILES_X)   // 16384
#define BATCH        32
#define TOTAL_TILES  (BATCH * TILES_PER_IMG)// 524288
#define TPB          256
#define NBLOCKS      (TOTAL_TILES / TPB)    // 2048 (exact)

__device__ float        g_partials[NBLOCKS];
__device__ unsigned int g_ticket = 0;       // reset by last block each launch

// Thresholds (NORMALIZE=True): thr_s = (50 / 2^(level_idx-1)) / 255
// Per-coefficient scale: weight_s / (3 * N_s)
#define THR1 (50.0f / (4.0f * 255.0f))
#define THR2 (50.0f / (2.0f * 255.0f))
#define THR3 (50.0f / 255.0f)
#define C1   (1.0f / (3.0f * 3.0f * 8388608.0f))
#define C2   (1.0f / (2.0f * 3.0f * 2097152.0f))
#define C3   (1.0f / (1.0f * 3.0f * 524288.0f))

__device__ __forceinline__ float band3(float a, float b, float c, float d, float thr,
                                       float* cA) {
    float s0 = a + b, s1 = c + d;
    float d0 = a - b, d1 = c - d;
    float cH = (s0 - s1) * 0.5f;
    float cV = (d0 + d1) * 0.5f;
    float cD = (d0 - d1) * 0.5f;
    *cA = (s0 + s1) * 0.5f;
    return fminf(fabsf(cH), thr) + fminf(fabsf(cV), thr) + fminf(fabsf(cD), thr);
}

__global__ void __launch_bounds__(TPB)
wavelet_fused_kernel(const float* __restrict__ pred, float* __restrict__ out) {
    const int tid = blockIdx.x * TPB + threadIdx.x;   // global tile id, exact fit
    const int b  = tid / TILES_PER_IMG;
    const int t  = tid - b * TILES_PER_IMG;
    const int ty = t / TILES_X;
    const int tx = t - ty * TILES_X;

    const float* base = pred + (size_t)b * (IMG * IMG) + (size_t)ty * 8 * IMG + (size_t)tx * 8;

    // Load the 8x8 tile as 16 independent float4 loads (high MLP).
    float x[8][8];
    #pragma unroll
    for (int row = 0; row < 8; ++row) {
        const float4 v0 = __ldg((const float4*)(base + (size_t)row * IMG));
        const float4 v1 = __ldg((const float4*)(base + (size_t)row * IMG) + 1);
        x[row][0] = v0.x; x[row][1] = v0.y; x[row][2] = v0.z; x[row][3] = v0.w;
        x[row][4] = v1.x; x[row][5] = v1.y; x[row][6] = v1.z; x[row][7] = v1.w;
    }

    // Level 1: 8x8 -> 4x4
    float A1[4][4];
    float s1 = 0.0f;
    #pragma unroll
    for (int i = 0; i < 4; ++i) {
        #pragma unroll
        for (int j = 0; j < 4; ++j) {
            s1 += band3(x[2*i][2*j], x[2*i][2*j+1], x[2*i+1][2*j], x[2*i+1][2*j+1],
                        THR1, &A1[i][j]);
        }
    }

    // Level 2: 4x4 -> 2x2
    float A2[2][2];
    float s2 = 0.0f;
    #pragma unroll
    for (int i = 0; i < 2; ++i) {
        #pragma unroll
        for (int j = 0; j < 2; ++j) {
            s2 += band3(A1[2*i][2*j], A1[2*i][2*j+1], A1[2*i+1][2*j], A1[2*i+1][2*j+1],
                        THR2, &A2[i][j]);
        }
    }

    // Level 3: 2x2 -> 1
    float cA3;
    float s3 = band3(A2[0][0], A2[0][1], A2[1][0], A2[1][1], THR3, &cA3);

    float val = s1 * C1 + s2 * C2 + s3 * C3;

    // Warp tree reduce
    #pragma unroll
    for (int off = 16; off > 0; off >>= 1)
        val += __shfl_xor_sync(0xffffffffu, val, off);

    __shared__ float warp_sums[TPB / 32];
    const int lane = threadIdx.x & 31;
    const int wid  = threadIdx.x >> 5;
    if (lane == 0) warp_sums[wid] = val;
    __syncthreads();          // the ONLY block-wide barrier

    // Warps 1..7 are done and retire here. Warp 0 finishes the block sum,
    // publishes it, and (if last) performs the grid reduction alone.
    if (wid == 0) {
        float s = (lane < TPB / 32) ? warp_sums[lane] : 0.0f;   // 8 values
        #pragma unroll
        for (int off = 4; off > 0; off >>= 1)
            s += __shfl_xor_sync(0xffffffffu, s, off);

        unsigned int ticket = 0;
        if (lane == 0) {
            g_partials[blockIdx.x] = s;   // ordered by the release below
            asm volatile("atom.acq_rel.gpu.global.add.u32 %0, [%1], %2;"
                         : "=r"(ticket)
                         : "l"(&g_ticket), "r"(1u)
                         : "memory");
        }
        ticket = __shfl_sync(0xffffffffu, ticket, 0);

        if (ticket == NBLOCKS - 1) {
            // Last block's warp 0: deterministic reduction of all partials.
            double acc = 0.0;
            #pragma unroll
            for (int i = 0; i < NBLOCKS / 32; ++i) {   // 64 per lane, fixed order
                float v;
                asm volatile("ld.acquire.gpu.global.f32 %0, [%1];"
                             : "=f"(v)
                             : "l"(g_partials + lane + i * 32)
                             : "memory");
                acc += (double)v;
            }
            // Warp tree reduce in double (fixed tree -> deterministic).
            #pragma unroll
            for (int off = 16; off > 0; off >>= 1) {
                acc += __shfl_xor_sync(0xffffffffu, acc, off);
            }
            if (lane == 0) {
                out[0] = (float)acc;
                g_ticket = 0;   // reset for next graph replay (determinism)
            }
        }
    }
}

extern "C" void kernel_launch(void* const* d_in, const int* in_sizes, int n_in,
                              void* d_out, int out_size) {
    const float* pred = (const float*)d_in[0];
    float* out = (float*)d_out;
    wavelet_fused_kernel<<<NBLOCKS, TPB>>>(pred, out);
}

// round 8
// speedup vs baseline: 1.4385x; 1.4385x over previous
#include <cuda_runtime.h>

// WaveletSparsityLoss: 3-level Haar DWT sparsity loss on [32,1,1024,1024] fp32.
// Single-pass streaming reduction: 3 Haar levels consume disjoint 8x8 input
// tiles. R5 structure (compile-time unrolled multi-tile per thread, fused
// last-block-done reduce with full-block exit barrier) with grid=1024 for
// near-perfect wave balance on 148 SMs (7/6.92 = 1.2% imbalance vs R5's 16%).

#define IMG          1024
#define TILES_X      128                    // 1024/8
#define TILES_PER_IMG (TILES_X * TILES_X)   // 16384
#define BATCH        32
#define TOTAL_TILES  (BATCH * TILES_PER_IMG)// 524288
#define TPB          256
#define TILES_PER_THREAD 2
#define NBLOCKS      (TOTAL_TILES / (TPB * TILES_PER_THREAD))  // 1024 (exact)

__device__ float        g_partials[NBLOCKS];
__device__ unsigned int g_ticket = 0;       // reset by last block each launch

// Thresholds (NORMALIZE=True): thr_s = (50 / 2^(level_idx-1)) / 255
// Per-coefficient scale: weight_s / (3 * N_s)
#define THR1 (50.0f / (4.0f * 255.0f))
#define THR2 (50.0f / (2.0f * 255.0f))
#define THR3 (50.0f / 255.0f)
#define C1   (1.0f / (3.0f * 3.0f * 8388608.0f))
#define C2   (1.0f / (2.0f * 3.0f * 2097152.0f))
#define C3   (1.0f / (1.0f * 3.0f * 524288.0f))

__device__ __forceinline__ float band3(float a, float b, float c, float d, float thr,
                                       float* cA) {
    float s0 = a + b, s1 = c + d;
    float d0 = a - b, d1 = c - d;
    float cH = (s0 - s1) * 0.5f;
    float cV = (d0 + d1) * 0.5f;
    float cD = (d0 - d1) * 0.5f;
    *cA = (s0 + s1) * 0.5f;
    return fminf(fabsf(cH), thr) + fminf(fabsf(cV), thr) + fminf(fabsf(cD), thr);
}

__device__ __forceinline__ float tile_loss(const float* __restrict__ pred, int tid) {
    const int b  = tid / TILES_PER_IMG;
    const int t  = tid - b * TILES_PER_IMG;
    const int ty = t / TILES_X;
    const int tx = t - ty * TILES_X;

    const float* base = pred + (size_t)b * (IMG * IMG) + (size_t)ty * 8 * IMG + (size_t)tx * 8;

    // Load the 8x8 tile as 16 independent float4 loads (high MLP).
    float x[8][8];
    #pragma unroll
    for (int row = 0; row < 8; ++row) {
        const float4 v0 = __ldg((const float4*)(base + (size_t)row * IMG));
        const float4 v1 = __ldg((const float4*)(base + (size_t)row * IMG) + 1);
        x[row][0] = v0.x; x[row][1] = v0.y; x[row][2] = v0.z; x[row][3] = v0.w;
        x[row][4] = v1.x; x[row][5] = v1.y; x[row][6] = v1.z; x[row][7] = v1.w;
    }

    // Level 1: 8x8 -> 4x4
    float A1[4][4];
    float s1 = 0.0f;
    #pragma unroll
    for (int i = 0; i < 4; ++i) {
        #pragma unroll
        for (int j = 0; j < 4; ++j) {
            s1 += band3(x[2*i][2*j], x[2*i][2*j+1], x[2*i+1][2*j], x[2*i+1][2*j+1],
                        THR1, &A1[i][j]);
        }
    }

    // Level 2: 4x4 -> 2x2
    float A2[2][2];
    float s2 = 0.0f;
    #pragma unroll
    for (int i = 0; i < 2; ++i) {
        #pragma unroll
        for (int j = 0; j < 2; ++j) {
            s2 += band3(A1[2*i][2*j], A1[2*i][2*j+1], A1[2*i+1][2*j], A1[2*i+1][2*j+1],
                        THR2, &A2[i][j]);
        }
    }

    // Level 3: 2x2 -> 1
    float cA3;
    float s3 = band3(A2[0][0], A2[0][1], A2[1][0], A2[1][1], THR3, &cA3);

    return s1 * C1 + s2 * C2 + s3 * C3;
}

__global__ void __launch_bounds__(TPB)
wavelet_fused_kernel(const float* __restrict__ pred, float* __restrict__ out) {
    const int tbase  = blockIdx.x * TPB + threadIdx.x;
    const int stride = NBLOCKS * TPB;                 // 262144

    float val = 0.0f;
    #pragma unroll
    for (int k = 0; k < TILES_PER_THREAD; ++k)
        val += tile_loss(pred, tbase + k * stride);

    // Warp tree reduce
    #pragma unroll
    for (int off = 16; off > 0; off >>= 1)
        val += __shfl_xor_sync(0xffffffffu, val, off);

    __shared__ float warp_sums[TPB / 32];
    const int lane = threadIdx.x & 31;
    const int wid  = threadIdx.x >> 5;
    if (lane == 0) warp_sums[wid] = val;
    __syncthreads();

    __shared__ bool is_last;
    if (threadIdx.x == 0) {
        float s = 0.0f;
        #pragma unroll
        for (int w = 0; w < TPB / 32; ++w) s += warp_sums[w];
        g_partials[blockIdx.x] = s;     // plain store; ordered by the release below
        unsigned int ticket;
        asm volatile("atom.acq_rel.gpu.global.add.u32 %0, [%1], %2;"
                     : "=r"(ticket)
                     : "l"(&g_ticket), "r"(1u)
                     : "memory");
        is_last = (ticket == NBLOCKS - 1);
    }
    __syncthreads();

    // Last arriving block: deterministic final reduction over all partials.
    if (is_last) {
        double acc = 0.0;
        #pragma unroll
        for (int i = 0; i < NBLOCKS / TPB; ++i) {       // 4 iterations
            float v;
            asm volatile("ld.acquire.gpu.global.f32 %0, [%1];"
                         : "=f"(v)
                         : "l"(g_partials + threadIdx.x + i * TPB)
                         : "memory");
            acc += (double)v;
        }

        __shared__ double sh[TPB];
        sh[threadIdx.x] = acc;
        __syncthreads();
        #pragma unroll
        for (int off = TPB / 2; off > 0; off >>= 1) {
            if (threadIdx.x < off) sh[threadIdx.x] += sh[threadIdx.x + off];
            __syncthreads();
        }
        if (threadIdx.x == 0) {
            out[0] = (float)sh[0];
            g_ticket = 0;   // reset for next graph replay (determinism)
        }
    }
}

extern "C" void kernel_launch(void* const* d_in, const int* in_sizes, int n_in,
                              void* d_out, int out_size) {
    const float* pred = (const float*)d_in[0];
    float* out = (float*)d_out;
    wavelet_fused_kernel<<<NBLOCKS, TPB>>>(pred, out);
}

// round 9
// speedup vs baseline: 1.6404x; 1.1404x over previous
#include <cuda_runtime.h>

// WaveletSparsityLoss: 3-level Haar DWT sparsity loss on [32,1,1024,1024] fp32.
// Two kernels: R1's unmodified streaming pass (fastest measured streaming
// phase, ~23.2us) + tiny reduce. The reduce kernel is launched with FULL PDL:
// k1 fires griddepcontrol.launch_dependents at block start (R3 was missing
// this -> no overlap), k2 waits via griddepcontrol.wait, so k2's launch/ramp
// overlaps k1's tail instead of serializing ~7us after it.

#define IMG          1024
#define TILES_X      128                    // 1024/8
#define TILES_PER_IMG (TILES_X * TILES_X)   // 16384
#define BATCH        32
#define TOTAL_TILES  (BATCH * TILES_PER_IMG)// 524288
#define TPB          256
#define NBLOCKS      (TOTAL_TILES / TPB)    // 2048 (exact)

// Scratch for deterministic two-stage reduction (no device allocation allowed).
__device__ float g_partials[NBLOCKS];

// Thresholds (NORMALIZE=True): thr_s = (50 / 2^(level_idx-1)) / 255
// Per-coefficient scale: weight_s / (3 * N_s)
#define THR1 (50.0f / (4.0f * 255.0f))
#define THR2 (50.0f / (2.0f * 255.0f))
#define THR3 (50.0f / 255.0f)
#define C1   (1.0f / (3.0f * 3.0f * 8388608.0f))
#define C2   (1.0f / (2.0f * 3.0f * 2097152.0f))
#define C3   (1.0f / (1.0f * 3.0f * 524288.0f))

__device__ __forceinline__ float band3(float a, float b, float c, float d, float thr,
                                       float* cA) {
    float s0 = a + b, s1 = c + d;
    float d0 = a - b, d1 = c - d;
    float cH = (s0 - s1) * 0.5f;
    float cV = (d0 + d1) * 0.5f;
    float cD = (d0 - d1) * 0.5f;
    *cA = (s0 + s1) * 0.5f;
    return fminf(fabsf(cH), thr) + fminf(fabsf(cV), thr) + fminf(fabsf(cD), thr);
}

__global__ void __launch_bounds__(TPB)
wavelet_tiles_kernel(const float* __restrict__ pred) {
    // PDL: allow the dependent (reduce) kernel to begin launching once all
    // CTAs of this grid have started. Correctness is enforced by the
    // consumer's griddepcontrol.wait, which waits for full grid completion.
    asm volatile("griddepcontrol.launch_dependents;");

    const int tid = blockIdx.x * TPB + threadIdx.x;   // global tile id, exact fit
    const int b  = tid / TILES_PER_IMG;
    const int t  = tid - b * TILES_PER_IMG;
    const int ty = t / TILES_X;
    const int tx = t - ty * TILES_X;

    const float* base = pred + (size_t)b * (IMG * IMG) + (size_t)ty * 8 * IMG + (size_t)tx * 8;

    // Load the 8x8 tile as 16 independent float4 loads (high MLP).
    float x[8][8];
    #pragma unroll
    for (int row = 0; row < 8; ++row) {
        const float4 v0 = __ldg((const float4*)(base + (size_t)row * IMG));
        const float4 v1 = __ldg((const float4*)(base + (size_t)row * IMG) + 1);
        x[row][0] = v0.x; x[row][1] = v0.y; x[row][2] = v0.z; x[row][3] = v0.w;
        x[row][4] = v1.x; x[row][5] = v1.y; x[row][6] = v1.z; x[row][7] = v1.w;
    }

    // Level 1: 8x8 -> 4x4
    float A1[4][4];
    float s1 = 0.0f;
    #pragma unroll
    for (int i = 0; i < 4; ++i) {
        #pragma unroll
        for (int j = 0; j < 4; ++j) {
            s1 += band3(x[2*i][2*j], x[2*i][2*j+1], x[2*i+1][2*j], x[2*i+1][2*j+1],
                        THR1, &A1[i][j]);
        }
    }

    // Level 2: 4x4 -> 2x2
    float A2[2][2];
    float s2 = 0.0f;
    #pragma unroll
    for (int i = 0; i < 2; ++i) {
        #pragma unroll
        for (int j = 0; j < 2; ++j) {
            s2 += band3(A1[2*i][2*j], A1[2*i][2*j+1], A1[2*i+1][2*j], A1[2*i+1][2*j+1],
                        THR2, &A2[i][j]);
        }
    }

    // Level 3: 2x2 -> 1
    float cA3;
    float s3 = band3(A2[0][0], A2[0][1], A2[1][0], A2[1][1], THR3, &cA3);

    float val = s1 * C1 + s2 * C2 + s3 * C3;

    // Warp tree reduce
    #pragma unroll
    for (int off = 16; off > 0; off >>= 1)
        val += __shfl_xor_sync(0xffffffffu, val, off);

    __shared__ float warp_sums[TPB / 32];
    const int lane = threadIdx.x & 31;
    const int wid  = threadIdx.x >> 5;
    if (lane == 0) warp_sums[wid] = val;
    __syncthreads();

    if (threadIdx.x == 0) {
        float s = 0.0f;
        #pragma unroll
        for (int w = 0; w < TPB / 32; ++w) s += warp_sums[w];
        g_partials[blockIdx.x] = s;
    }
}

__global__ void __launch_bounds__(TPB)
reduce_final_kernel(float* __restrict__ out) {
    // PDL: launched early (overlapping k1); block here until the producer
    // grid is fully complete and its memory is visible.
    asm volatile("griddepcontrol.wait;");

    // 2048 partials, 256 threads -> 8 each, deterministic fixed order.
    double acc = 0.0;
    #pragma unroll
    for (int i = 0; i < NBLOCKS / TPB; ++i)            // 8 iterations
        acc += (double)g_partials[threadIdx.x + i * TPB];

    // Warp-level double reduction.
    #pragma unroll
    for (int off = 16; off > 0; off >>= 1)
        acc += __shfl_xor_sync(0xffffffffu, acc, off);

    __shared__ double wsum[TPB / 32];                  // 8 warps
    const int lane = threadIdx.x & 31;
    const int wid  = threadIdx.x >> 5;
    if (lane == 0) wsum[wid] = acc;
    __syncthreads();

    if (wid == 0) {
        double v = (lane < TPB / 32) ? wsum[lane] : 0.0;
        #pragma unroll
        for (int off = 4; off > 0; off >>= 1)
            v += __shfl_xor_sync(0xffffffffu, v, off);
        if (lane == 0) out[0] = (float)v;
    }
}

extern "C" void kernel_launch(void* const* d_in, const int* in_sizes, int n_in,
                              void* d_out, int out_size) {
    const float* pred = (const float*)d_in[0];
    float* out = (float*)d_out;

    wavelet_tiles_kernel<<<NBLOCKS, TPB>>>(pred);

    // Dependent launch: overlaps k1 (waits inside via griddepcontrol.wait).
    cudaLaunchConfig_t cfg = {};
    cfg.gridDim  = dim3(1, 1, 1);
    cfg.blockDim = dim3(TPB, 1, 1);
    cfg.dynamicSmemBytes = 0;
    cfg.stream = 0;
    cudaLaunchAttribute attrs[1];
    attrs[0].id = cudaLaunchAttributeProgrammaticStreamSerialization;
    attrs[0].val.programmaticStreamSerializationAllowed = 1;
    cfg.attrs = attrs;
    cfg.numAttrs = 1;
    cudaLaunchKernelEx(&cfg, reduce_final_kernel, out);
}